// round 1
// baseline (speedup 1.0000x reference)
#include <cuda_runtime.h>
#include <math.h>

#define KW   9
#define PAD  4
#define TX   32
#define TY   8
#define SX   (TX + 2*PAD)   // 40
#define SY   (TY + 2*PAD)   // 16
#define HH   256
#define WW   256
#define CC   3

// diag = sqrt(256^2 + 256^2)
#define INV_DIAG (1.0f / 362.03867196751236f)
#define SIGMA_MIN 0.5f
#define SIGMA_RANGE 9.5f      // SIGMA_MAX - SIGMA_MIN
#define PI_F 3.14159265358979323846f

__global__ __launch_bounds__(TX * TY)
void adaptive_log_conv(const float* __restrict__ x,
                       const float* __restrict__ foa,
                       float* __restrict__ out)
{
    __shared__ float sm[CC][SY][SX];

    const int b   = blockIdx.z;
    const int bx0 = blockIdx.x * TX;
    const int by0 = blockIdx.y * TY;
    const int tid = threadIdx.y * TX + threadIdx.x;

    const float* xb = x + (size_t)b * CC * HH * WW;

    // cooperative load of 3 channel tiles with reflect padding (pad=4 < H, single reflection)
    #pragma unroll
    for (int i = tid; i < CC * SY * SX; i += TX * TY) {
        int c   = i / (SY * SX);
        int rem = i - c * (SY * SX);
        int ly  = rem / SX;
        int lx  = rem - ly * SX;
        int gy  = by0 + ly - PAD;
        int gx  = bx0 + lx - PAD;
        gy = (gy < 0) ? -gy : ((gy >= HH) ? (2 * HH - 2 - gy) : gy);
        gx = (gx < 0) ? -gx : ((gx >= WW) ? (2 * WW - 2 - gx) : gx);
        sm[c][ly][lx] = __ldg(&xb[(c * HH + gy) * WW + gx]);
    }
    __syncthreads();

    const int px = bx0 + threadIdx.x;
    const int py = by0 + threadIdx.y;

    // per-pixel LoG parameters
    const float fx = foa[b * 2 + 0];
    const float fy = foa[b * 2 + 1];
    const float ddx = (float)px - fx;
    const float ddy = (float)py - fy;
    const float dist = sqrtf(ddx * ddx + ddy * ddy);
    const float dn = dist * INV_DIAG;
    const float s  = SIGMA_MIN + SIGMA_RANGE * dn;
    const float s2 = s * s;
    const float inv2s2 = 0.5f / s2;
    const float factor = -1.0f / (PI_F * s2 * s2);
    const float common = factor * sqrtf(s) * dist;

    // 15 unique r_sq values over the 9x9 stencil -> 15 weights, register-resident
    float wq[33];
    #define MKW(Q) do { float t = (float)(Q) * inv2s2; \
                        wq[Q] = common * (1.0f - t) * __expf(-t); } while (0)
    MKW(0);  MKW(1);  MKW(2);  MKW(4);  MKW(5);
    MKW(8);  MKW(9);  MKW(10); MKW(13); MKW(16);
    MKW(17); MKW(18); MKW(20); MKW(25); MKW(32);
    #undef MKW

    float acc0 = 0.0f, acc1 = 0.0f, acc2 = 0.0f;
    #pragma unroll
    for (int oy = 0; oy < KW; oy++) {
        #pragma unroll
        for (int ox = 0; ox < KW; ox++) {
            const int q = (oy - PAD) * (oy - PAD) + (ox - PAD) * (ox - PAD);
            const float w = wq[q];
            acc0 = fmaf(sm[0][threadIdx.y + oy][threadIdx.x + ox], w, acc0);
            acc1 = fmaf(sm[1][threadIdx.y + oy][threadIdx.x + ox], w, acc1);
            acc2 = fmaf(sm[2][threadIdx.y + oy][threadIdx.x + ox], w, acc2);
        }
    }

    float* ob = out + (size_t)b * CC * HH * WW;
    ob[(0 * HH + py) * WW + px] = acc0;
    ob[(1 * HH + py) * WW + px] = acc1;
    ob[(2 * HH + py) * WW + px] = acc2;
}

extern "C" void kernel_launch(void* const* d_in, const int* in_sizes, int n_in,
                              void* d_out, int out_size)
{
    const float* x   = (const float*)d_in[0];
    const float* foa = (const float*)d_in[1];
    float* out = (float*)d_out;

    dim3 block(TX, TY, 1);
    dim3 grid(WW / TX, HH / TY, 4);
    adaptive_log_conv<<<grid, block>>>(x, foa, out);
}